// round 15
// baseline (speedup 1.0000x reference)
#include <cuda_runtime.h>
#include <cuda_fp16.h>
#include <math.h>
#include <stdint.h>

#define Bb   8
#define Tt   1024
#define DIMf 512
#define Hh   8
#define DKd  64
#define DHh  512
#define NHn  64
#define EPSf 1e-5f

// ---------------- scratch ---------------------------------------------------
__device__ __half g_qkvh[Bb * 3 * DHh * Tt];    // fp16 q, exp(k), v
__device__ __half g_Wh  [1536 * 512];
__device__ __half g_xh  [Bb * Tt * DIMf];
__device__ __half g_Woh [512 * 512];
__device__ __half g_midh[Bb * DHh * Tt];
__device__ __half g_ctxh[NHn * DKd * DKd];      // reduced+normalized ctx fp16 [n][d][e]
__device__ float  g_ctxp[8 * NHn * DKd * DKd];  // unnormalized ctx partials
__device__ float  g_Zp  [8 * NHn * DKd];        // Z partials [s][n][d]
__device__ float  g_S   [NHn * Tt];
__device__ float  g_P   [DKd * Tt];
__device__ float  g_bns [DKd * 512];            // [e][n*8+s]
__device__ float  g_bnq [DKd * 512];
__device__ float  g_sc  [DKd];
__device__ float  g_sh  [DKd];

// ---------------- PTX helpers -----------------------------------------------
__device__ __forceinline__ void cp16s(uint32_t s, const void* gmem) {
    asm volatile("cp.async.cg.shared.global [%0], [%1], 16;\n" :: "r"(s), "l"(gmem));
}
#define CP_COMMIT() asm volatile("cp.async.commit_group;\n")
#define CP_WAIT0()  asm volatile("cp.async.wait_group 0;\n")
#define CP_WAIT1()  asm volatile("cp.async.wait_group 1;\n")

__device__ __forceinline__ uint32_t smem_u32(const void* p) {
    uint32_t a;
    asm("{ .reg .u64 t; cvta.to.shared.u64 t, %1; cvt.u32.u64 %0, t; }" : "=r"(a) : "l"(p));
    return a;
}

__device__ __forceinline__ void mma_f16(float* c, const uint32_t* a, const uint32_t* b) {
    asm volatile(
        "mma.sync.aligned.m16n8k16.row.col.f32.f16.f16.f32 "
        "{%0,%1,%2,%3}, {%4,%5,%6,%7}, {%8,%9}, {%0,%1,%2,%3};\n"
        : "+f"(c[0]), "+f"(c[1]), "+f"(c[2]), "+f"(c[3])
        : "r"(a[0]), "r"(a[1]), "r"(a[2]), "r"(a[3]), "r"(b[0]), "r"(b[1]));
}

__device__ __forceinline__ void ldsm_x4(uint32_t* r, uint32_t addr) {
    asm volatile("ldmatrix.sync.aligned.m8n8.x4.shared.b16 {%0,%1,%2,%3}, [%4];"
        : "=r"(r[0]), "=r"(r[1]), "=r"(r[2]), "=r"(r[3]) : "r"(addr));
}
__device__ __forceinline__ void ldsm_x4t(uint32_t* r, uint32_t addr) {
    asm volatile("ldmatrix.sync.aligned.m8n8.x4.trans.shared.b16 {%0,%1,%2,%3}, [%4];"
        : "=r"(r[0]), "=r"(r[1]), "=r"(r[2]), "=r"(r[3]) : "r"(addr));
}

// ---------------- prep: rel-pos prefix + fp16 conversion (MLP=4) ------------
__global__ void k_pre(const float* __restrict__ relpos, const float* __restrict__ W,
                      const float* __restrict__ x, const float* __restrict__ Wo) {
    int bid = blockIdx.x, tid = threadIdx.x;
    if (bid < 256) {
        int gid = bid * 256 + tid;
        int d = gid >> 10, t = gid & 1023;
        int lo = 31 - t;    if (lo < 0)  lo = 0;
        int hi = 1054 - t;  if (hi > 62) hi = 62;
        float s = 0.f;
        for (int ri = lo; ri <= hi; ri++) s += relpos[ri * DKd + d];
        g_P[d * Tt + t] = s;
        return;
    }
    long i0 = (long)(bid - 256) * 1024 + tid * 4;
    const float4* src;
    __half* dst;
    long base;
    if (i0 < 196608)       { src = (const float4*)W;  dst = g_Wh;  base = 0; }
    else if (i0 < 1245184) { src = (const float4*)x;  dst = g_xh;  base = 196608; }
    else                   { src = (const float4*)Wo; dst = g_Woh; base = 1245184; }
    long j0 = i0 - base;
    float4 v0 = src[j0], v1 = src[j0 + 1], v2 = src[j0 + 2], v3 = src[j0 + 3];
    uint2* d2 = (uint2*)dst;
    #define CVT4(vv, jj) do {                                \
        __half2 p0 = __floats2half2_rn((vv).x, (vv).y);      \
        __half2 p1 = __floats2half2_rn((vv).z, (vv).w);      \
        uint2 u;                                             \
        u.x = *(const uint32_t*)&p0;                         \
        u.y = *(const uint32_t*)&p1;                         \
        d2[jj] = u;                                          \
    } while (0)
    CVT4(v0, j0); CVT4(v1, j0 + 1); CVT4(v2, j0 + 2); CVT4(v3, j0 + 3);
    #undef CVT4
}

// ===================== GEMM1 (fp16 m16n8k16, TN) -> fp16 out ================
// k-third blocks (blockIdx.y in [4,8)) store exp(k) instead of k.
__global__ __launch_bounds__(128, 2)
void k_gemm_qkv_h() {
    __shared__ __half As[2][128 * 40];
    __shared__ __half Bs[2][128 * 40];

    int tid = threadIdx.x, warp = tid >> 5, lane = tid & 31;
    int wm = (warp >> 1) * 64, wn = (warp & 1) * 64;
    int m0 = blockIdx.y * 128, n0 = blockIdx.x * 128;
    bool isK = (blockIdx.y >= 4) && (blockIdx.y < 8);
    const __half* A  = g_Wh;
    const __half* Bm = g_xh + (long)blockIdx.z * Tt * DIMf;
    __half*       C  = g_qkvh + (long)blockIdx.z * 1536 * Tt;

    float acc[4][8][4];
    #pragma unroll
    for (int i = 0; i < 4; i++)
        #pragma unroll
        for (int j = 0; j < 8; j++)
            #pragma unroll
            for (int r = 0; r < 4; r++) acc[i][j][r] = 0.f;

    int g = lane >> 3, r8 = lane & 7;
    int a_off = ((g & 1) * 8 + r8) * 40 + (g >> 1) * 8;
    int b_off = ((g >> 1) * 8 + r8) * 40 + (g & 1) * 8;

    uint32_t sAs = smem_u32(As), sBs = smem_u32(Bs);

    const __half* arow = A  + (long)(m0 + tid) * 512;
    const __half* brow = Bm + (long)(n0 + tid) * 512;

    {
        uint32_t da = sAs + (uint32_t)(tid * 40) * 2;
        uint32_t db = sBs + (uint32_t)(tid * 40) * 2;
        #pragma unroll
        for (int q = 0; q < 4; q++) {
            cp16s(da + q * 16, arow + q * 8);
            cp16s(db + q * 16, brow + q * 8);
        }
        CP_COMMIT();
    }

    for (int kt = 0; kt < 16; kt++) {
        int buf = kt & 1;
        if (kt + 1 < 16) {
            uint32_t da = sAs + (uint32_t)((buf ^ 1) * 5120 + tid * 40) * 2;
            uint32_t db = sBs + (uint32_t)((buf ^ 1) * 5120 + tid * 40) * 2;
            const __half* ap = arow + (kt + 1) * 32;
            const __half* bp = brow + (kt + 1) * 32;
            #pragma unroll
            for (int q = 0; q < 4; q++) {
                cp16s(da + q * 16, ap + q * 8);
                cp16s(db + q * 16, bp + q * 8);
            }
            CP_COMMIT();
            CP_WAIT1();
        } else {
            CP_WAIT0();
        }
        __syncthreads();

        #pragma unroll
        for (int ks = 0; ks < 2; ks++) {
            uint32_t a[4][4], b[8][2];
            #pragma unroll
            for (int i = 0; i < 4; i++)
                ldsm_x4(a[i], sAs + (uint32_t)((buf * 5120 + (wm + i * 16) * 40 + ks * 16) + a_off) * 2);
            #pragma unroll
            for (int p = 0; p < 4; p++) {
                uint32_t r[4];
                ldsm_x4(r, sBs + (uint32_t)((buf * 5120 + (wn + p * 16) * 40 + ks * 16) + b_off) * 2);
                b[p * 2][0] = r[0]; b[p * 2][1] = r[1];
                b[p * 2 + 1][0] = r[2]; b[p * 2 + 1][1] = r[3];
            }
            #pragma unroll
            for (int i = 0; i < 4; i++)
                #pragma unroll
                for (int j = 0; j < 8; j++)
                    mma_f16(acc[i][j], a[i], b[j]);
        }
        __syncthreads();
    }

    int lrow = lane >> 2;
    #pragma unroll
    for (int i = 0; i < 4; i++) {
        #pragma unroll
        for (int j = 0; j < 8; j++) {
            int m = m0 + wm + i * 16 + lrow;
            int n = n0 + wn + j * 8 + (lane & 3) * 2;
            float r0 = acc[i][j][0], r1 = acc[i][j][1];
            float r2 = acc[i][j][2], r3 = acc[i][j][3];
            if (isK) {
                r0 = exp2f(r0 * 1.44269504f);
                r1 = exp2f(r1 * 1.44269504f);
                r2 = exp2f(r2 * 1.44269504f);
                r3 = exp2f(r3 * 1.44269504f);
            }
            __half2 h0 = __floats2half2_rn(r0, r1);
            __half2 h1 = __floats2half2_rn(r2, r3);
            *(__half2*)&C[(long)m * Tt + n]       = h0;
            *(__half2*)&C[(long)(m + 8) * Tt + n] = h1;
        }
    }
}

// ===================== ctx + S + BN partials (fp16 ldsm/mma) ================
// block (s, n): t-slice s*128..s*128+127; K already holds exp(k)
__global__ __launch_bounds__(128)
void k_ctx() {
    int s = blockIdx.x, n = blockIdx.y;
    int b = n >> 3, h = n & 7;
    const __half* Qh = g_qkvh + ((long)b * 1536 + h * 64) * Tt;
    const __half* Kh = g_qkvh + ((long)b * 1536 + 512  + h * 64) * Tt;
    const __half* Vh = g_qkvh + ((long)b * 1536 + 1024 + h * 64) * Tt;

    __shared__ __half Ksm[64 * 136];
    __shared__ __half Vsm[64 * 136];
    __shared__ float sS[128];

    int tid = threadIdx.x;
    int warp = tid >> 5, lane = tid & 31;
    int wm = (warp >> 1) * 32, wn = (warp & 1) * 32;
    int lrow = lane >> 2;
    int g = lane >> 3, r8 = lane & 7;
    int a_off = ((g & 1) * 8 + r8) * 136 + (g >> 1) * 8;
    int b_off = ((g >> 1) * 8 + r8) * 136 + (g & 1) * 8;
    int t0 = s * 128;
    int tc = tid & 15, dl = tid >> 4;     // tc: t chunk of 8 halves, dl: row group

    uint32_t sK = smem_u32(Ksm), sV = smem_u32(Vsm);

    // ---- phase 1: S for this slice ----
    {
        int t = t0 + tid;
        float S = 0.f;
        #pragma unroll
        for (int d = 0; d < 64; d++)
            S += __half2float(Qh[(long)d * Tt + t]) * g_P[d * Tt + t];
        g_S[n * Tt + t] = S;
        sS[tid] = S;
    }

    // ---- stage exp(k) (plain copy), v; Z partials from staged halves ----
    float zacc[8];
    #pragma unroll
    for (int dd = 0; dd < 8; dd++) {
        int d = dd * 8 + dl;
        uint4 ku = *(const uint4*)&Kh[(long)d * Tt + t0 + tc * 8];
        *(uint4*)&Ksm[d * 136 + tc * 8] = ku;
        const __half2* kp = (const __half2*)&ku;
        float zp = 0.f;
        #pragma unroll
        for (int p = 0; p < 4; p++)
            zp += __half2float(kp[p].x) + __half2float(kp[p].y);
        #pragma unroll
        for (int off = 8; off; off >>= 1)
            zp += __shfl_xor_sync(0xffffffffu, zp, off);
        zacc[dd] = zp;
        uint4 vu = *(const uint4*)&Vh[(long)d * Tt + t0 + tc * 8];
        *(uint4*)&Vsm[d * 136 + tc * 8] = vu;
    }
    __syncthreads();

    // ---- fp16 mma: ctx[d][e] += expk[d][t] * v[e][t] over this slice ----
    float acc[2][4][4];
    #pragma unroll
    for (int i = 0; i < 2; i++)
        #pragma unroll
        for (int j = 0; j < 4; j++)
            #pragma unroll
            for (int r = 0; r < 4; r++) acc[i][j][r] = 0.f;

    #pragma unroll
    for (int kc = 0; kc < 8; kc++) {       // t-chunks of 16
        uint32_t a[2][4], bfr[4][2];
        #pragma unroll
        for (int i = 0; i < 2; i++)
            ldsm_x4(a[i], sK + (uint32_t)((wm + i * 16) * 136 + kc * 16 + a_off) * 2);
        #pragma unroll
        for (int p = 0; p < 2; p++) {
            uint32_t r[4];
            ldsm_x4(r, sV + (uint32_t)((wn + p * 16) * 136 + kc * 16 + b_off) * 2);
            bfr[p * 2][0] = r[0]; bfr[p * 2][1] = r[1];
            bfr[p * 2 + 1][0] = r[2]; bfr[p * 2 + 1][1] = r[3];
        }
        #pragma unroll
        for (int i = 0; i < 2; i++)
            #pragma unroll
            for (int j = 0; j < 4; j++)
                mma_f16(acc[i][j], a[i], bfr[j]);
    }

    // ---- write Z partials ----
    if (tc == 0) {
        #pragma unroll
        for (int dd = 0; dd < 8; dd++) {
            int d = dd * 8 + dl;
            g_Zp[(long)s * 4096 + n * 64 + d] = zacc[dd];
        }
    }

    // ---- write ctx partials ----
    float* dst = g_ctxp + ((long)(s * NHn + n)) * 4096;
    #pragma unroll
    for (int i = 0; i < 2; i++) {
        #pragma unroll
        for (int j = 0; j < 4; j++) {
            int d = wm + i * 16 + lrow;
            int e = wn + j * 8 + (lane & 3) * 2;
            *(float2*)&dst[d * 64 + e]       = make_float2(acc[i][j][0], acc[i][j][1]);
            *(float2*)&dst[(d + 8) * 64 + e] = make_float2(acc[i][j][2], acc[i][j][3]);
        }
    }

    // ---- phase 3: BN partials of v*S (v from smem) ----
    #pragma unroll
    for (int i = 0; i < 16; i++) {
        int e = warp * 16 + i;
        float sum = 0.f, sq = 0.f;
        #pragma unroll
        for (int it = 0; it < 4; it++) {
            int tt = it * 32 + lane;
            float r = __half2float(Vsm[e * 136 + tt]) * sS[tt];
            sum += r; sq += r * r;
        }
        #pragma unroll
        for (int o = 16; o; o >>= 1) {
            sum += __shfl_xor_sync(0xffffffffu, sum, o);
            sq  += __shfl_xor_sync(0xffffffffu, sq,  o);
        }
        if (lane == 0) {
            g_bns[e * 512 + n * 8 + s] = sum;
            g_bnq[e * 512 + n * 8 + s] = sq;
        }
    }
}

// ---------------- BN reduce + ctx reduce/normalize -> fp16 ------------------
// block i: BN scale/shift for channel e=i  AND  ctx reduce for head n=i
__global__ __launch_bounds__(256)
void k_bnred(const float* __restrict__ gamma, const float* __restrict__ beta) {
    int i = blockIdx.x;                 // 0..63
    int tid = threadIdx.x;              // 256
    __shared__ float sZ[64];

    // ---- part A: BN reduce for channel e = i ----
    {
        int e = i;
        float s = g_bns[e * 512 + tid] + g_bns[e * 512 + 256 + tid];
        float q = g_bnq[e * 512 + tid] + g_bnq[e * 512 + 256 + tid];
        #pragma unroll
        for (int o = 16; o; o >>= 1) {
            s += __shfl_xor_sync(0xffffffffu, s, o);
            q += __shfl_xor_sync(0xffffffffu, q, o);
        }
        __shared__ float ws[8], wq[8];
        if ((tid & 31) == 0) { ws[tid >> 5] = s; wq[tid >> 5] = q; }
        __syncthreads();
        if (tid == 0) {
            float S = 0.f, Q = 0.f;
            #pragma unroll
            for (int w = 0; w < 8; w++) { S += ws[w]; Q += wq[w]; }
            const float cnt = (float)(NHn * Tt);
            float mu  = S / cnt;
            float var = Q / cnt - mu * mu;
            float sc  = gamma[e] * rsqrtf(var + EPSf);
            g_sc[e] = sc;
            g_sh[e] = beta[e] - mu * sc;
        }
    }

    // ---- part B: ctx reduce + Z-normalize for head n = i -> fp16 [d][e] ----
    int n = i;
    if (tid < 64) {
        float z = 0.f;
        #pragma unroll
        for (int s = 0; s < 8; s++) z += g_Zp[(long)s * 4096 + n * 64 + tid];
        sZ[tid] = 1.f / z;
    }
    __syncthreads();

    for (int i4 = tid; i4 < 1024; i4 += 256) {
        int d = i4 >> 4, e4 = (i4 & 15) * 4;
        float4 a = ((const float4*)(g_ctxp + (long)n * 4096))[i4];
        #pragma unroll
        for (int p = 1; p < 8; p++) {
            float4 x = ((const float4*)(g_ctxp + (long)(p * NHn + n) * 4096))[i4];
            a.x += x.x; a.y += x.y; a.z += x.z; a.w += x.w;
        }
        float iz = sZ[d];
        __half2 h0 = __floats2half2_rn(a.x * iz, a.y * iz);
        __half2 h1 = __floats2half2_rn(a.z * iz, a.w * iz);
        uint2 u;
        u.x = *(const uint32_t*)&h0;
        u.y = *(const uint32_t*)&h1;
        *(uint2*)&g_ctxh[(long)n * 4096 + d * 64 + e4] = u;
    }
}

// ---------------- content via tensor cores + fused BN epilogue --------------
__global__ __launch_bounds__(128)
void k_content() {
    int n = blockIdx.y;
    int t0 = blockIdx.x * 128;
    int b = n >> 3, h = n & 7;
    const __half* Qh = g_qkvh + ((long)b * 1536 + h * 64) * Tt;
    const __half* Vh = g_qkvh + ((long)b * 1536 + 1024 + h * 64) * Tt;

    __shared__ __half Csm[64 * 72];     // [e][d]
    __shared__ __half Qsm[64 * 136];    // [d][t]
    __shared__ float sS[128], ssc[64], ssh[64];

    int tid = threadIdx.x, warp = tid >> 5, lane = tid & 31;

    if (tid < 64) {
        ssc[tid] = g_sc[tid];
        ssh[tid] = g_sh[tid];
    }
    sS[tid] = g_S[n * Tt + t0 + tid];

    // ---- stage ctx fp16 [d][e] -> Csm[e][d] (transpose in smem) ----
    for (int c = tid; c < 1024; c += 128) {
        int d = c >> 4, e4 = (c & 15) * 4;
        uint2 u = *(const uint2*)&g_ctxh[(long)n * 4096 + d * 64 + e4];
        const __half* hp = (const __half*)&u;
        Csm[(e4 + 0) * 72 + d] = hp[0];
        Csm[(e4 + 1) * 72 + d] = hp[1];
        Csm[(e4 + 2) * 72 + d] = hp[2];
        Csm[(e4 + 3) * 72 + d] = hp[3];
    }

    // ---- stage q tile [64 d][128 t] ----
    for (int c = tid; c < 1024; c += 128) {
        int d = c >> 4, tq = (c & 15) * 8;
        *(uint4*)&Qsm[d * 136 + tq] = *(const uint4*)&Qh[(long)d * Tt + t0 + tq];
    }
    __syncthreads();

    // ---- mma: [64 e] x [128 t] = A[e][d] * B[d][t] ----
    int wm = (warp >> 1) * 32, wn = (warp & 1) * 64;
    int g = lane >> 3, r8 = lane & 7;
    int a_off  = ((g & 1) * 8 + r8) * 72  + (g >> 1) * 8;
    int bt_off = ((g & 1) * 8 + r8) * 136 + (g >> 1) * 8;
    uint32_t sC = smem_u32(Csm), sQ = smem_u32(Qsm);

    float acc[2][8][4];
    #pragma unroll
    for (int i = 0; i < 2; i++)
        #pragma unroll
        for (int j = 0; j < 8; j++)
            #pragma unroll
            for (int r = 0; r < 4; r++) acc[i][j][r] = 0.f;

    #pragma unroll
    for (int kc = 0; kc < 4; kc++) {      // d chunks of 16
        uint32_t a[2][4], bq[8][2];
        #pragma unroll
        for (int i = 0; i < 2; i++)
            ldsm_x4(a[i], sC + (uint32_t)((wm + i * 16) * 72 + kc * 16 + a_off) * 2);
        #pragma unroll
        for (int p = 0; p < 4; p++) {
            uint32_t r[4];
            ldsm_x4t(r, sQ + (uint32_t)((kc * 16) * 136 + wn + p * 16 + bt_off) * 2);
            bq[p * 2][0] = r[0]; bq[p * 2][1] = r[1];
            bq[p * 2 + 1][0] = r[2]; bq[p * 2 + 1][1] = r[3];
        }
        #pragma unroll
        for (int i = 0; i < 2; i++)
            #pragma unroll
            for (int j = 0; j < 8; j++)
                mma_f16(acc[i][j], a[i], bq[j]);
    }

    // ---- epilogue: += v*S*sc + sh, store fp16 midh ----
    __half* Dst = g_midh + ((long)b * 512 + h * 64) * Tt;
    int lrow = lane >> 2;
    #pragma unroll
    for (int i = 0; i < 2; i++) {
        #pragma unroll
        for (int j = 0; j < 8; j++) {
            int e0 = wm + i * 16 + lrow;
            int tt = wn + j * 8 + (lane & 3) * 2;
            int t  = t0 + tt;
            float S0 = sS[tt], S1 = sS[tt + 1];
            {
                __half2 vh = *(const __half2*)&Vh[(long)e0 * Tt + t];
                float r0 = acc[i][j][0] + __half2float(vh.x) * S0 * ssc[e0] + ssh[e0];
                float r1 = acc[i][j][1] + __half2float(vh.y) * S1 * ssc[e0] + ssh[e0];
                *(__half2*)&Dst[(long)e0 * Tt + t] = __floats2half2_rn(r0, r1);
            }
            {
                int e1 = e0 + 8;
                __half2 vh = *(const __half2*)&Vh[(long)e1 * Tt + t];
                float r2 = acc[i][j][2] + __half2float(vh.x) * S0 * ssc[e1] + ssh[e1];
                float r3 = acc[i][j][3] + __half2float(vh.y) * S1 * ssc[e1] + ssh[e1];
                *(__half2*)&Dst[(long)e1 * Tt + t] = __floats2half2_rn(r2, r3);
            }
        }
    }
}

// ===================== GEMM2 (fp16 m16n8k16, NN via trans) =================
__global__ __launch_bounds__(128, 2)
void k_gemm_out_h(const float* __restrict__ bias, float* __restrict__ out) {
    __shared__ __half As[2][128 * 40];
    __shared__ __half Bs[2][32 * 136];

    int tid = threadIdx.x, warp = tid >> 5, lane = tid & 31;
    int wm = (warp >> 1) * 64, wn = (warp & 1) * 64;
    int m0 = blockIdx.y * 128, n0 = blockIdx.x * 128;
    const __half* A  = g_Woh;
    const __half* Bm = g_midh + (long)blockIdx.z * 512 * Tt;
    float*        C  = out    + (long)blockIdx.z * 512 * Tt;

    float acc[4][8][4];
    #pragma unroll
    for (int i = 0; i < 4; i++)
        #pragma unroll
        for (int j = 0; j < 8; j++)
            #pragma unroll
            for (int r = 0; r < 4; r++) acc[i][j][r] = 0.f;

    int g = lane >> 3, r8 = lane & 7;
    int a_off  = ((g & 1) * 8 + r8) * 40 + (g >> 1) * 8;
    int bt_off = ((g & 1) * 8 + r8) * 136 + (g >> 1) * 8;

    uint32_t sAs = smem_u32(As), sBs = smem_u32(Bs);

    const __half* arow = A + (long)(m0 + tid) * 512;
    int brw = tid >> 2, bq = tid & 3;
    const __half* brow = Bm + (long)brw * Tt + n0;

    {
        uint32_t da = sAs + (uint32_t)(tid * 40) * 2;
        #pragma unroll
        for (int q = 0; q < 4; q++) cp16s(da + q * 16, arow + q * 8);
        uint32_t db = sBs + (uint32_t)(brw * 136) * 2;
        #pragma unroll
        for (int s = 0; s < 4; s++) {
            int qq = bq * 4 + s;
            cp16s(db + qq * 16, brow + qq * 8);
        }
        CP_COMMIT();
    }

    for (int kt = 0; kt < 16; kt++) {
        int buf = kt & 1;
        if (kt + 1 < 16) {
            int k0 = (kt + 1) * 32;
            uint32_t da = sAs + (uint32_t)((buf ^ 1) * 5120 + tid * 40) * 2;
            const __half* ap = arow + k0;
            #pragma unroll
            for (int q = 0; q < 4; q++) cp16s(da + q * 16, ap + q * 8);
            uint32_t db = sBs + (uint32_t)((buf ^ 1) * 4352 + brw * 136) * 2;
            const __half* bp = brow + (long)k0 * Tt;
            #pragma unroll
            for (int s = 0; s < 4; s++) {
                int qq = bq * 4 + s;
                cp16s(db + qq * 16, bp + qq * 8);
            }
            CP_COMMIT();
            CP_WAIT1();
        } else {
            CP_WAIT0();
        }
        __syncthreads();

        #pragma unroll
        for (int ks = 0; ks < 2; ks++) {
            uint32_t a[4][4], b[8][2];
            #pragma unroll
            for (int i = 0; i < 4; i++)
                ldsm_x4(a[i], sAs + (uint32_t)((buf * 5120 + (wm + i * 16) * 40 + ks * 16) + a_off) * 2);
            #pragma unroll
            for (int p = 0; p < 4; p++) {
                uint32_t r[4];
                ldsm_x4t(r, sBs + (uint32_t)((buf * 4352 + (ks * 16) * 136 + wn + p * 16) + bt_off) * 2);
                b[p * 2][0] = r[0]; b[p * 2][1] = r[1];
                b[p * 2 + 1][0] = r[2]; b[p * 2 + 1][1] = r[3];
            }
            #pragma unroll
            for (int i = 0; i < 4; i++)
                #pragma unroll
                for (int j = 0; j < 8; j++)
                    mma_f16(acc[i][j], a[i], b[j]);
        }
        __syncthreads();
    }

    int lrow = lane >> 2;
    #pragma unroll
    for (int i = 0; i < 4; i++) {
        #pragma unroll
        for (int j = 0; j < 8; j++) {
            int m = m0 + wm + i * 16 + lrow;
            int n = n0 + wn + j * 8 + (lane & 3) * 2;
            float bv0 = bias[m], bv1 = bias[m + 8];
            *(float2*)&C[(long)m * Tt + n] =
                make_float2(acc[i][j][0] + bv0, acc[i][j][1] + bv0);
            *(float2*)&C[(long)(m + 8) * Tt + n] =
                make_float2(acc[i][j][2] + bv1, acc[i][j][3] + bv1);
        }
    }
}

// ---------------- launcher ---------------------------------------------------
extern "C" void kernel_launch(void* const* d_in, const int* in_sizes, int n_in,
                              void* d_out, int out_size) {
    const float* x      = (const float*)d_in[0];
    const float* Wqkv   = (const float*)d_in[1];
    const float* Wout   = (const float*)d_in[2];
    const float* bout   = (const float*)d_in[3];
    const float* relpos = (const float*)d_in[4];
    const float* gamma  = (const float*)d_in[5];
    const float* beta   = (const float*)d_in[6];
    float* out = (float*)d_out;

    k_pre<<<256 + 1280, 256>>>(relpos, Wqkv, x, Wout);
    k_gemm_qkv_h<<<dim3(8, 12, 8), 128>>>();
    k_ctx<<<dim3(8, 64), 128>>>();
    k_bnred<<<64, 256>>>(gamma, beta);
    k_content<<<dim3(8, 64), 128>>>();
    k_gemm_out_h<<<dim3(8, 4, 8), 128>>>(bout, out);
}

// round 16
// speedup vs baseline: 1.0151x; 1.0151x over previous
#include <cuda_runtime.h>
#include <cuda_fp16.h>
#include <math.h>
#include <stdint.h>

#define Bb   8
#define Tt   1024
#define DIMf 512
#define Hh   8
#define DKd  64
#define DHh  512
#define NHn  64
#define EPSf 1e-5f

// ---------------- scratch ---------------------------------------------------
__device__ __half g_qkvh[Bb * 3 * DHh * Tt];    // fp16 q, exp(k), v
__device__ __half g_Wh  [1536 * 512];
__device__ __half g_xh  [Bb * Tt * DIMf];
__device__ __half g_Woh [512 * 512];
__device__ __half g_midh[Bb * DHh * Tt];
__device__ __half g_ctxh[NHn * DKd * DKd];      // reduced+normalized ctx fp16 [n][d][e]
__device__ float  g_ctxp[8 * NHn * DKd * DKd];  // unnormalized ctx partials
__device__ float  g_Zp  [8 * NHn * DKd];        // Z partials [s][n][d]
__device__ float  g_S   [NHn * Tt];
__device__ float  g_P   [DKd * Tt];
__device__ float  g_bns [DKd * 512];            // [e][n*8+s]
__device__ float  g_bnq [DKd * 512];
__device__ float  g_sc  [DKd];
__device__ float  g_sh  [DKd];

// ---------------- PTX helpers -----------------------------------------------
__device__ __forceinline__ void cp16s(uint32_t s, const void* gmem) {
    asm volatile("cp.async.cg.shared.global [%0], [%1], 16;\n" :: "r"(s), "l"(gmem));
}
#define CP_COMMIT() asm volatile("cp.async.commit_group;\n")
#define CP_WAIT0()  asm volatile("cp.async.wait_group 0;\n")
#define CP_WAIT1()  asm volatile("cp.async.wait_group 1;\n")

__device__ __forceinline__ uint32_t smem_u32(const void* p) {
    uint32_t a;
    asm("{ .reg .u64 t; cvta.to.shared.u64 t, %1; cvt.u32.u64 %0, t; }" : "=r"(a) : "l"(p));
    return a;
}

__device__ __forceinline__ void mma_f16(float* c, const uint32_t* a, const uint32_t* b) {
    asm volatile(
        "mma.sync.aligned.m16n8k16.row.col.f32.f16.f16.f32 "
        "{%0,%1,%2,%3}, {%4,%5,%6,%7}, {%8,%9}, {%0,%1,%2,%3};\n"
        : "+f"(c[0]), "+f"(c[1]), "+f"(c[2]), "+f"(c[3])
        : "r"(a[0]), "r"(a[1]), "r"(a[2]), "r"(a[3]), "r"(b[0]), "r"(b[1]));
}

__device__ __forceinline__ void ldsm_x4(uint32_t* r, uint32_t addr) {
    asm volatile("ldmatrix.sync.aligned.m8n8.x4.shared.b16 {%0,%1,%2,%3}, [%4];"
        : "=r"(r[0]), "=r"(r[1]), "=r"(r[2]), "=r"(r[3]) : "r"(addr));
}
__device__ __forceinline__ void ldsm_x4t(uint32_t* r, uint32_t addr) {
    asm volatile("ldmatrix.sync.aligned.m8n8.x4.trans.shared.b16 {%0,%1,%2,%3}, [%4];"
        : "=r"(r[0]), "=r"(r[1]), "=r"(r[2]), "=r"(r[3]) : "r"(addr));
}

// ---------------- prep: rel-pos prefix + fp16 conversion (MLP=4) ------------
__global__ void k_pre(const float* __restrict__ relpos, const float* __restrict__ W,
                      const float* __restrict__ x, const float* __restrict__ Wo) {
    int bid = blockIdx.x, tid = threadIdx.x;
    if (bid < 256) {
        int gid = bid * 256 + tid;
        int d = gid >> 10, t = gid & 1023;
        int lo = 31 - t;    if (lo < 0)  lo = 0;
        int hi = 1054 - t;  if (hi > 62) hi = 62;
        float s = 0.f;
        for (int ri = lo; ri <= hi; ri++) s += relpos[ri * DKd + d];
        g_P[d * Tt + t] = s;
        return;
    }
    long i0 = (long)(bid - 256) * 1024 + tid * 4;
    const float4* src;
    __half* dst;
    long base;
    if (i0 < 196608)       { src = (const float4*)W;  dst = g_Wh;  base = 0; }
    else if (i0 < 1245184) { src = (const float4*)x;  dst = g_xh;  base = 196608; }
    else                   { src = (const float4*)Wo; dst = g_Woh; base = 1245184; }
    long j0 = i0 - base;
    float4 v0 = src[j0], v1 = src[j0 + 1], v2 = src[j0 + 2], v3 = src[j0 + 3];
    uint2* d2 = (uint2*)dst;
    #define CVT4(vv, jj) do {                                \
        __half2 p0 = __floats2half2_rn((vv).x, (vv).y);      \
        __half2 p1 = __floats2half2_rn((vv).z, (vv).w);      \
        uint2 u;                                             \
        u.x = *(const uint32_t*)&p0;                         \
        u.y = *(const uint32_t*)&p1;                         \
        d2[jj] = u;                                          \
    } while (0)
    CVT4(v0, j0); CVT4(v1, j0 + 1); CVT4(v2, j0 + 2); CVT4(v3, j0 + 3);
    #undef CVT4
}

// ===================== GEMM1 (fp16 m16n8k16, TN) -> fp16 out ================
// k-third blocks (blockIdx.y in [4,8)) store exp(k) instead of k.
__global__ __launch_bounds__(128, 2)
void k_gemm_qkv_h() {
    __shared__ __half As[2][128 * 40];
    __shared__ __half Bs[2][128 * 40];

    int tid = threadIdx.x, warp = tid >> 5, lane = tid & 31;
    int wm = (warp >> 1) * 64, wn = (warp & 1) * 64;
    int m0 = blockIdx.y * 128, n0 = blockIdx.x * 128;
    bool isK = (blockIdx.y >= 4) && (blockIdx.y < 8);
    const __half* A  = g_Wh;
    const __half* Bm = g_xh + (long)blockIdx.z * Tt * DIMf;
    __half*       C  = g_qkvh + (long)blockIdx.z * 1536 * Tt;

    float acc[4][8][4];
    #pragma unroll
    for (int i = 0; i < 4; i++)
        #pragma unroll
        for (int j = 0; j < 8; j++)
            #pragma unroll
            for (int r = 0; r < 4; r++) acc[i][j][r] = 0.f;

    int g = lane >> 3, r8 = lane & 7;
    int a_off = ((g & 1) * 8 + r8) * 40 + (g >> 1) * 8;
    int b_off = ((g >> 1) * 8 + r8) * 40 + (g & 1) * 8;

    uint32_t sAs = smem_u32(As), sBs = smem_u32(Bs);

    const __half* arow = A  + (long)(m0 + tid) * 512;
    const __half* brow = Bm + (long)(n0 + tid) * 512;

    {
        uint32_t da = sAs + (uint32_t)(tid * 40) * 2;
        uint32_t db = sBs + (uint32_t)(tid * 40) * 2;
        #pragma unroll
        for (int q = 0; q < 4; q++) {
            cp16s(da + q * 16, arow + q * 8);
            cp16s(db + q * 16, brow + q * 8);
        }
        CP_COMMIT();
    }

    for (int kt = 0; kt < 16; kt++) {
        int buf = kt & 1;
        if (kt + 1 < 16) {
            uint32_t da = sAs + (uint32_t)((buf ^ 1) * 5120 + tid * 40) * 2;
            uint32_t db = sBs + (uint32_t)((buf ^ 1) * 5120 + tid * 40) * 2;
            const __half* ap = arow + (kt + 1) * 32;
            const __half* bp = brow + (kt + 1) * 32;
            #pragma unroll
            for (int q = 0; q < 4; q++) {
                cp16s(da + q * 16, ap + q * 8);
                cp16s(db + q * 16, bp + q * 8);
            }
            CP_COMMIT();
            CP_WAIT1();
        } else {
            CP_WAIT0();
        }
        __syncthreads();

        #pragma unroll
        for (int ks = 0; ks < 2; ks++) {
            uint32_t a[4][4], b[8][2];
            #pragma unroll
            for (int i = 0; i < 4; i++)
                ldsm_x4(a[i], sAs + (uint32_t)((buf * 5120 + (wm + i * 16) * 40 + ks * 16) + a_off) * 2);
            #pragma unroll
            for (int p = 0; p < 4; p++) {
                uint32_t r[4];
                ldsm_x4(r, sBs + (uint32_t)((buf * 5120 + (wn + p * 16) * 40 + ks * 16) + b_off) * 2);
                b[p * 2][0] = r[0]; b[p * 2][1] = r[1];
                b[p * 2 + 1][0] = r[2]; b[p * 2 + 1][1] = r[3];
            }
            #pragma unroll
            for (int i = 0; i < 4; i++)
                #pragma unroll
                for (int j = 0; j < 8; j++)
                    mma_f16(acc[i][j], a[i], b[j]);
        }
        __syncthreads();
    }

    int lrow = lane >> 2;
    #pragma unroll
    for (int i = 0; i < 4; i++) {
        #pragma unroll
        for (int j = 0; j < 8; j++) {
            int m = m0 + wm + i * 16 + lrow;
            int n = n0 + wn + j * 8 + (lane & 3) * 2;
            float r0 = acc[i][j][0], r1 = acc[i][j][1];
            float r2 = acc[i][j][2], r3 = acc[i][j][3];
            if (isK) {
                r0 = exp2f(r0 * 1.44269504f);
                r1 = exp2f(r1 * 1.44269504f);
                r2 = exp2f(r2 * 1.44269504f);
                r3 = exp2f(r3 * 1.44269504f);
            }
            __half2 h0 = __floats2half2_rn(r0, r1);
            __half2 h1 = __floats2half2_rn(r2, r3);
            *(__half2*)&C[(long)m * Tt + n]       = h0;
            *(__half2*)&C[(long)(m + 8) * Tt + n] = h1;
        }
    }
}

// ===================== ctx + S + BN partials (fp16 ldsm/mma) ================
// block (s, n): t-slice s*128..s*128+127; K already holds exp(k)
__global__ __launch_bounds__(128)
void k_ctx() {
    int s = blockIdx.x, n = blockIdx.y;
    int b = n >> 3, h = n & 7;
    const __half* Qh = g_qkvh + ((long)b * 1536 + h * 64) * Tt;
    const __half* Kh = g_qkvh + ((long)b * 1536 + 512  + h * 64) * Tt;
    const __half* Vh = g_qkvh + ((long)b * 1536 + 1024 + h * 64) * Tt;

    __shared__ __half Ksm[64 * 136];
    __shared__ __half Vsm[64 * 136];
    __shared__ float sS[128];

    int tid = threadIdx.x;
    int warp = tid >> 5, lane = tid & 31;
    int wm = (warp >> 1) * 32, wn = (warp & 1) * 32;
    int lrow = lane >> 2;
    int g = lane >> 3, r8 = lane & 7;
    int a_off = ((g & 1) * 8 + r8) * 136 + (g >> 1) * 8;
    int b_off = ((g >> 1) * 8 + r8) * 136 + (g & 1) * 8;
    int t0 = s * 128;
    int tc = tid & 15, dl = tid >> 4;     // tc: t chunk of 8 halves, dl: row group

    uint32_t sK = smem_u32(Ksm), sV = smem_u32(Vsm);

    // ---- phase 1: S for this slice ----
    {
        int t = t0 + tid;
        float S = 0.f;
        #pragma unroll
        for (int d = 0; d < 64; d++)
            S += __half2float(Qh[(long)d * Tt + t]) * g_P[d * Tt + t];
        g_S[n * Tt + t] = S;
        sS[tid] = S;
    }

    // ---- stage exp(k) (plain copy), v; Z partials from staged halves ----
    float zacc[8];
    #pragma unroll
    for (int dd = 0; dd < 8; dd++) {
        int d = dd * 8 + dl;
        uint4 ku = *(const uint4*)&Kh[(long)d * Tt + t0 + tc * 8];
        *(uint4*)&Ksm[d * 136 + tc * 8] = ku;
        const __half2* kp = (const __half2*)&ku;
        float zp = 0.f;
        #pragma unroll
        for (int p = 0; p < 4; p++)
            zp += __half2float(kp[p].x) + __half2float(kp[p].y);
        #pragma unroll
        for (int off = 8; off; off >>= 1)
            zp += __shfl_xor_sync(0xffffffffu, zp, off);
        zacc[dd] = zp;
        uint4 vu = *(const uint4*)&Vh[(long)d * Tt + t0 + tc * 8];
        *(uint4*)&Vsm[d * 136 + tc * 8] = vu;
    }
    __syncthreads();

    // ---- fp16 mma: ctx[d][e] += expk[d][t] * v[e][t] over this slice ----
    float acc[2][4][4];
    #pragma unroll
    for (int i = 0; i < 2; i++)
        #pragma unroll
        for (int j = 0; j < 4; j++)
            #pragma unroll
            for (int r = 0; r < 4; r++) acc[i][j][r] = 0.f;

    #pragma unroll
    for (int kc = 0; kc < 8; kc++) {       // t-chunks of 16
        uint32_t a[2][4], bfr[4][2];
        #pragma unroll
        for (int i = 0; i < 2; i++)
            ldsm_x4(a[i], sK + (uint32_t)((wm + i * 16) * 136 + kc * 16 + a_off) * 2);
        #pragma unroll
        for (int p = 0; p < 2; p++) {
            uint32_t r[4];
            ldsm_x4(r, sV + (uint32_t)((wn + p * 16) * 136 + kc * 16 + b_off) * 2);
            bfr[p * 2][0] = r[0]; bfr[p * 2][1] = r[1];
            bfr[p * 2 + 1][0] = r[2]; bfr[p * 2 + 1][1] = r[3];
        }
        #pragma unroll
        for (int i = 0; i < 2; i++)
            #pragma unroll
            for (int j = 0; j < 4; j++)
                mma_f16(acc[i][j], a[i], bfr[j]);
    }

    // ---- write Z partials ----
    if (tc == 0) {
        #pragma unroll
        for (int dd = 0; dd < 8; dd++) {
            int d = dd * 8 + dl;
            g_Zp[(long)s * 4096 + n * 64 + d] = zacc[dd];
        }
    }

    // ---- write ctx partials ----
    float* dst = g_ctxp + ((long)(s * NHn + n)) * 4096;
    #pragma unroll
    for (int i = 0; i < 2; i++) {
        #pragma unroll
        for (int j = 0; j < 4; j++) {
            int d = wm + i * 16 + lrow;
            int e = wn + j * 8 + (lane & 3) * 2;
            *(float2*)&dst[d * 64 + e]       = make_float2(acc[i][j][0], acc[i][j][1]);
            *(float2*)&dst[(d + 8) * 64 + e] = make_float2(acc[i][j][2], acc[i][j][3]);
        }
    }

    // ---- phase 3: BN partials of v*S (v from smem) ----
    #pragma unroll
    for (int i = 0; i < 16; i++) {
        int e = warp * 16 + i;
        float sum = 0.f, sq = 0.f;
        #pragma unroll
        for (int it = 0; it < 4; it++) {
            int tt = it * 32 + lane;
            float r = __half2float(Vsm[e * 136 + tt]) * sS[tt];
            sum += r; sq += r * r;
        }
        #pragma unroll
        for (int o = 16; o; o >>= 1) {
            sum += __shfl_xor_sync(0xffffffffu, sum, o);
            sq  += __shfl_xor_sync(0xffffffffu, sq,  o);
        }
        if (lane == 0) {
            g_bns[e * 512 + n * 8 + s] = sum;
            g_bnq[e * 512 + n * 8 + s] = sq;
        }
    }
}

// ---------------- BN reduce + ctx reduce/normalize -> fp16 (grid 256) -------
// block i<64: BN scale/shift for channel e=i
// every block: ctx reduce quarter (head n=i>>2, quarter i&3)
__global__ __launch_bounds__(256)
void k_bnred(const float* __restrict__ gamma, const float* __restrict__ beta) {
    int i = blockIdx.x;                 // 0..255
    int tid = threadIdx.x;              // 256
    __shared__ float sZ[64];

    // ---- part A: BN reduce for channel e = i (blocks 0..63 only) ----
    if (i < 64) {
        int e = i;
        float s = g_bns[e * 512 + tid] + g_bns[e * 512 + 256 + tid];
        float q = g_bnq[e * 512 + tid] + g_bnq[e * 512 + 256 + tid];
        #pragma unroll
        for (int o = 16; o; o >>= 1) {
            s += __shfl_xor_sync(0xffffffffu, s, o);
            q += __shfl_xor_sync(0xffffffffu, q, o);
        }
        __shared__ float ws[8], wq[8];
        if ((tid & 31) == 0) { ws[tid >> 5] = s; wq[tid >> 5] = q; }
        __syncthreads();
        if (tid == 0) {
            float S = 0.f, Q = 0.f;
            #pragma unroll
            for (int w = 0; w < 8; w++) { S += ws[w]; Q += wq[w]; }
            const float cnt = (float)(NHn * Tt);
            float mu  = S / cnt;
            float var = Q / cnt - mu * mu;
            float sc  = gamma[e] * rsqrtf(var + EPSf);
            g_sc[e] = sc;
            g_sh[e] = beta[e] - mu * sc;
        }
    }

    // ---- part B: ctx reduce + Z-normalize for head n = i>>2, quarter i&3 ---
    int n = i >> 2, qt = i & 3;
    if (tid < 64) {
        float z = 0.f;
        #pragma unroll
        for (int s = 0; s < 8; s++) z += g_Zp[(long)s * 4096 + n * 64 + tid];
        sZ[tid] = 1.f / z;
    }
    __syncthreads();

    {
        int i4 = qt * 256 + tid;            // one float4 per thread
        int d = i4 >> 4, e4 = (i4 & 15) * 4;
        float4 a = ((const float4*)(g_ctxp + (long)n * 4096))[i4];
        #pragma unroll
        for (int p = 1; p < 8; p++) {
            float4 x = ((const float4*)(g_ctxp + (long)(p * NHn + n) * 4096))[i4];
            a.x += x.x; a.y += x.y; a.z += x.z; a.w += x.w;
        }
        float iz = sZ[d];
        __half2 h0 = __floats2half2_rn(a.x * iz, a.y * iz);
        __half2 h1 = __floats2half2_rn(a.z * iz, a.w * iz);
        uint2 u;
        u.x = *(const uint32_t*)&h0;
        u.y = *(const uint32_t*)&h1;
        *(uint2*)&g_ctxh[(long)n * 4096 + d * 64 + e4] = u;
    }
}

// ---------------- content via tensor cores + fused BN epilogue --------------
__global__ __launch_bounds__(128)
void k_content() {
    int n = blockIdx.y;
    int t0 = blockIdx.x * 128;
    int b = n >> 3, h = n & 7;
    const __half* Qh = g_qkvh + ((long)b * 1536 + h * 64) * Tt;
    const __half* Vh = g_qkvh + ((long)b * 1536 + 1024 + h * 64) * Tt;

    __shared__ __half Csm[64 * 72];     // [e][d]
    __shared__ __half Qsm[64 * 136];    // [d][t]
    __shared__ float sS[128], ssc[64], ssh[64];

    int tid = threadIdx.x, warp = tid >> 5, lane = tid & 31;

    if (tid < 64) {
        ssc[tid] = g_sc[tid];
        ssh[tid] = g_sh[tid];
    }
    sS[tid] = g_S[n * Tt + t0 + tid];

    // ---- stage ctx fp16 [d][e] -> Csm[e][d] (transpose in smem) ----
    for (int c = tid; c < 1024; c += 128) {
        int d = c >> 4, e4 = (c & 15) * 4;
        uint2 u = *(const uint2*)&g_ctxh[(long)n * 4096 + d * 64 + e4];
        const __half* hp = (const __half*)&u;
        Csm[(e4 + 0) * 72 + d] = hp[0];
        Csm[(e4 + 1) * 72 + d] = hp[1];
        Csm[(e4 + 2) * 72 + d] = hp[2];
        Csm[(e4 + 3) * 72 + d] = hp[3];
    }

    // ---- stage q tile [64 d][128 t] ----
    for (int c = tid; c < 1024; c += 128) {
        int d = c >> 4, tq = (c & 15) * 8;
        *(uint4*)&Qsm[d * 136 + tq] = *(const uint4*)&Qh[(long)d * Tt + t0 + tq];
    }
    __syncthreads();

    // ---- mma: [64 e] x [128 t] = A[e][d] * B[d][t] ----
    int wm = (warp >> 1) * 32, wn = (warp & 1) * 64;
    int g = lane >> 3, r8 = lane & 7;
    int a_off  = ((g & 1) * 8 + r8) * 72  + (g >> 1) * 8;
    int bt_off = ((g & 1) * 8 + r8) * 136 + (g >> 1) * 8;
    uint32_t sC = smem_u32(Csm), sQ = smem_u32(Qsm);

    float acc[2][8][4];
    #pragma unroll
    for (int i = 0; i < 2; i++)
        #pragma unroll
        for (int j = 0; j < 8; j++)
            #pragma unroll
            for (int r = 0; r < 4; r++) acc[i][j][r] = 0.f;

    #pragma unroll
    for (int kc = 0; kc < 4; kc++) {      // d chunks of 16
        uint32_t a[2][4], bq[8][2];
        #pragma unroll
        for (int i = 0; i < 2; i++)
            ldsm_x4(a[i], sC + (uint32_t)((wm + i * 16) * 72 + kc * 16 + a_off) * 2);
        #pragma unroll
        for (int p = 0; p < 4; p++) {
            uint32_t r[4];
            ldsm_x4t(r, sQ + (uint32_t)((kc * 16) * 136 + wn + p * 16 + bt_off) * 2);
            bq[p * 2][0] = r[0]; bq[p * 2][1] = r[1];
            bq[p * 2 + 1][0] = r[2]; bq[p * 2 + 1][1] = r[3];
        }
        #pragma unroll
        for (int i = 0; i < 2; i++)
            #pragma unroll
            for (int j = 0; j < 8; j++)
                mma_f16(acc[i][j], a[i], bq[j]);
    }

    // ---- epilogue: += v*S*sc + sh, store fp16 midh ----
    __half* Dst = g_midh + ((long)b * 512 + h * 64) * Tt;
    int lrow = lane >> 2;
    #pragma unroll
    for (int i = 0; i < 2; i++) {
        #pragma unroll
        for (int j = 0; j < 8; j++) {
            int e0 = wm + i * 16 + lrow;
            int tt = wn + j * 8 + (lane & 3) * 2;
            int t  = t0 + tt;
            float S0 = sS[tt], S1 = sS[tt + 1];
            {
                __half2 vh = *(const __half2*)&Vh[(long)e0 * Tt + t];
                float r0 = acc[i][j][0] + __half2float(vh.x) * S0 * ssc[e0] + ssh[e0];
                float r1 = acc[i][j][1] + __half2float(vh.y) * S1 * ssc[e0] + ssh[e0];
                *(__half2*)&Dst[(long)e0 * Tt + t] = __floats2half2_rn(r0, r1);
            }
            {
                int e1 = e0 + 8;
                __half2 vh = *(const __half2*)&Vh[(long)e1 * Tt + t];
                float r2 = acc[i][j][2] + __half2float(vh.x) * S0 * ssc[e1] + ssh[e1];
                float r3 = acc[i][j][3] + __half2float(vh.y) * S1 * ssc[e1] + ssh[e1];
                *(__half2*)&Dst[(long)e1 * Tt + t] = __floats2half2_rn(r2, r3);
            }
        }
    }
}

// ===================== GEMM2 (fp16 m16n8k16, NN via trans) =================
__global__ __launch_bounds__(128, 2)
void k_gemm_out_h(const float* __restrict__ bias, float* __restrict__ out) {
    __shared__ __half As[2][128 * 40];
    __shared__ __half Bs[2][32 * 136];

    int tid = threadIdx.x, warp = tid >> 5, lane = tid & 31;
    int wm = (warp >> 1) * 64, wn = (warp & 1) * 64;
    int m0 = blockIdx.y * 128, n0 = blockIdx.x * 128;
    const __half* A  = g_Woh;
    const __half* Bm = g_midh + (long)blockIdx.z * 512 * Tt;
    float*        C  = out    + (long)blockIdx.z * 512 * Tt;

    float acc[4][8][4];
    #pragma unroll
    for (int i = 0; i < 4; i++)
        #pragma unroll
        for (int j = 0; j < 8; j++)
            #pragma unroll
            for (int r = 0; r < 4; r++) acc[i][j][r] = 0.f;

    int g = lane >> 3, r8 = lane & 7;
    int a_off  = ((g & 1) * 8 + r8) * 40 + (g >> 1) * 8;
    int bt_off = ((g & 1) * 8 + r8) * 136 + (g >> 1) * 8;

    uint32_t sAs = smem_u32(As), sBs = smem_u32(Bs);

    const __half* arow = A + (long)(m0 + tid) * 512;
    int brw = tid >> 2, bq = tid & 3;
    const __half* brow = Bm + (long)brw * Tt + n0;

    {
        uint32_t da = sAs + (uint32_t)(tid * 40) * 2;
        #pragma unroll
        for (int q = 0; q < 4; q++) cp16s(da + q * 16, arow + q * 8);
        uint32_t db = sBs + (uint32_t)(brw * 136) * 2;
        #pragma unroll
        for (int s = 0; s < 4; s++) {
            int qq = bq * 4 + s;
            cp16s(db + qq * 16, brow + qq * 8);
        }
        CP_COMMIT();
    }

    for (int kt = 0; kt < 16; kt++) {
        int buf = kt & 1;
        if (kt + 1 < 16) {
            int k0 = (kt + 1) * 32;
            uint32_t da = sAs + (uint32_t)((buf ^ 1) * 5120 + tid * 40) * 2;
            const __half* ap = arow + k0;
            #pragma unroll
            for (int q = 0; q < 4; q++) cp16s(da + q * 16, ap + q * 8);
            uint32_t db = sBs + (uint32_t)((buf ^ 1) * 4352 + brw * 136) * 2;
            const __half* bp = brow + (long)k0 * Tt;
            #pragma unroll
            for (int s = 0; s < 4; s++) {
                int qq = bq * 4 + s;
                cp16s(db + qq * 16, bp + qq * 8);
            }
            CP_COMMIT();
            CP_WAIT1();
        } else {
            CP_WAIT0();
        }
        __syncthreads();

        #pragma unroll
        for (int ks = 0; ks < 2; ks++) {
            uint32_t a[4][4], b[8][2];
            #pragma unroll
            for (int i = 0; i < 4; i++)
                ldsm_x4(a[i], sAs + (uint32_t)((buf * 5120 + (wm + i * 16) * 40 + ks * 16) + a_off) * 2);
            #pragma unroll
            for (int p = 0; p < 4; p++) {
                uint32_t r[4];
                ldsm_x4t(r, sBs + (uint32_t)((buf * 4352 + (ks * 16) * 136 + wn + p * 16) + bt_off) * 2);
                b[p * 2][0] = r[0]; b[p * 2][1] = r[1];
                b[p * 2 + 1][0] = r[2]; b[p * 2 + 1][1] = r[3];
            }
            #pragma unroll
            for (int i = 0; i < 4; i++)
                #pragma unroll
                for (int j = 0; j < 8; j++)
                    mma_f16(acc[i][j], a[i], b[j]);
        }
        __syncthreads();
    }

    int lrow = lane >> 2;
    #pragma unroll
    for (int i = 0; i < 4; i++) {
        #pragma unroll
        for (int j = 0; j < 8; j++) {
            int m = m0 + wm + i * 16 + lrow;
            int n = n0 + wn + j * 8 + (lane & 3) * 2;
            float bv0 = bias[m], bv1 = bias[m + 8];
            *(float2*)&C[(long)m * Tt + n] =
                make_float2(acc[i][j][0] + bv0, acc[i][j][1] + bv0);
            *(float2*)&C[(long)(m + 8) * Tt + n] =
                make_float2(acc[i][j][2] + bv1, acc[i][j][3] + bv1);
        }
    }
}

// ---------------- launcher ---------------------------------------------------
extern "C" void kernel_launch(void* const* d_in, const int* in_sizes, int n_in,
                              void* d_out, int out_size) {
    const float* x      = (const float*)d_in[0];
    const float* Wqkv   = (const float*)d_in[1];
    const float* Wout   = (const float*)d_in[2];
    const float* bout   = (const float*)d_in[3];
    const float* relpos = (const float*)d_in[4];
    const float* gamma  = (const float*)d_in[5];
    const float* beta   = (const float*)d_in[6];
    float* out = (float*)d_out;

    k_pre<<<256 + 1280, 256>>>(relpos, Wqkv, x, Wout);
    k_gemm_qkv_h<<<dim3(8, 12, 8), 128>>>();
    k_ctx<<<dim3(8, 64), 128>>>();
    k_bnred<<<256, 256>>>(gamma, beta);
    k_content<<<dim3(8, 64), 128>>>();
    k_gemm_out_h<<<dim3(8, 4, 8), 128>>>(bout, out);
}